// round 12
// baseline (speedup 1.0000x reference)
#include <cuda_runtime.h>
#include <cstdint>

// RNN: B=512, T=512, D=64, H=512, O=1
// R7: cluster k-split (2 CTAs/cluster) + intra-CTA k-split (2 warp-groups).
//  512 thr/CTA (4 warps/SMSP). wg owns 128 k-rows; thread = 2 cols x 8 rows.
//  wg1 partials reduced into wg0 via conflict-free float4 smem scratch.
//  DSMEM exchange of foreign j-half unchanged from R6.

#define BSZ 512
#define TSZ 512
#define DSZ 64
#define HSZ 512
#define KH  256       // k-rows per CTA
#define CROWS 8       // batch rows per cluster
#define NTHR 512
#define NCTA 128
#define KCG  40       // cached W_h rows per k-group (80/CTA)
#define KSTR 88       // streamed rows per group
#define UPF  8        // 88 % 8 == 0
#define KSTRIDE 12    // h smem k-stride in floats

// smem floats: whc 2*40*512=40960 | hsm 256*12=3072 | xbf 2*128*16=4096
//              red 4*256*4=4096 | wd 512   -> 52736 f = 210944 B
#define SMEM_MAIN_BYTES ((2*KCG*HSZ + KH*KSTRIDE + 2*128*16 + 4*256*4 + 512) * 4)

#define TT 16
#define SMEM_XW_BYTES ((DSZ * HSZ + TT * DSZ * 4) * 4)
#define NTHRX 256

__device__ float g_xw[(size_t)TSZ * BSZ * HSZ];   // [T][B][H]

typedef unsigned long long u64;

__device__ __forceinline__ void ffma2(u64& acc, u64 a, u64 b) {
    asm("fma.rn.f32x2 %0, %1, %2, %0;" : "+l"(acc) : "l"(a), "l"(b));
}
__device__ __forceinline__ u64 pack2(float lo, float hi) {
    u64 r; asm("mov.b64 %0, {%1, %2};" : "=l"(r) : "f"(lo), "f"(hi)); return r;
}
__device__ __forceinline__ void unpack2(float& lo, float& hi, u64 v) {
    asm("mov.b64 {%0, %1}, %2;" : "=f"(lo), "=f"(hi) : "l"(v));
}
__device__ __forceinline__ uint32_t smem_u32(const void* p) {
    uint32_t a;
    asm("{ .reg .u64 t; cvta.to.shared.u64 t, %1; cvt.u32.u64 %0, t; }"
        : "=r"(a) : "l"(p));
    return a;
}
__device__ __forceinline__ uint32_t mapa_peer(uint32_t addr, uint32_t peer) {
    uint32_t r;
    asm("mapa.shared::cluster.u32 %0, %1, %2;" : "=r"(r) : "r"(addr), "r"(peer));
    return r;
}
__device__ __forceinline__ float4 ld_cluster_f4(uint32_t a) {
    float4 v;
    asm volatile("ld.shared::cluster.v4.f32 {%0,%1,%2,%3}, [%4];"
                 : "=f"(v.x), "=f"(v.y), "=f"(v.z), "=f"(v.w) : "r"(a));
    return v;
}
__device__ __forceinline__ float ld_cluster_f32(uint32_t a) {
    float v;
    asm volatile("ld.shared::cluster.f32 %0, [%1];" : "=f"(v) : "r"(a));
    return v;
}
#define CLUSTER_SYNC() do { \
    asm volatile("barrier.cluster.arrive.aligned;" ::: "memory"); \
    asm volatile("barrier.cluster.wait.aligned;"   ::: "memory"); \
} while (0)

// ---------------------------------------------------------------------------
// Kernel 1: XW = x @ W_x + b_rnn   (unchanged from R6)
// ---------------------------------------------------------------------------
__global__ __launch_bounds__(NTHRX, 1)
void xw_kernel(const float* __restrict__ x,
               const float* __restrict__ Wx,
               const float* __restrict__ brnn)
{
    extern __shared__ float smem[];
    float* wx_s = smem;
    float* xs   = wx_s + DSZ * HSZ;

    const int tid = threadIdx.x;
    const int t0  = blockIdx.x * TT;
    const int b0  = blockIdx.y * 4;

    {
        const float4* g = reinterpret_cast<const float4*>(Wx);
        float4* d = reinterpret_cast<float4*>(wx_s);
        #pragma unroll 8
        for (int i = tid; i < DSZ * HSZ / 4; i += NTHRX) d[i] = g[i];
    }
    #pragma unroll
    for (int i = 0; i < TT * DSZ * 4 / NTHRX; i++) {
        int idx = tid + i * NTHRX;
        int d = idx & 63;
        int t = (idx >> 6) & (TT - 1);
        int r = idx >> 10;
        xs[(t * DSZ + d) * 4 + r] = x[((size_t)(b0 + r) * TSZ + t0 + t) * DSZ + d];
    }
    __syncthreads();

    const float2* wx2 = reinterpret_cast<const float2*>(wx_s) + tid;
    float bA = brnn[2 * tid], bB = brnn[2 * tid + 1];
    u64 bA2 = pack2(bA, bA), bB2 = pack2(bB, bB);

    float2* xwo = reinterpret_cast<float2*>(g_xw);

    for (int t = 0; t < TT; t++) {
        u64 a01 = bA2, a23 = bA2, c01 = bB2, c23 = bB2;
        const ulonglong2* xv = reinterpret_cast<const ulonglong2*>(xs + t * DSZ * 4);
        #pragma unroll 8
        for (int k = 0; k < DSZ; k++) {
            float2 w = wx2[k * (HSZ / 2)];
            ulonglong2 hv = xv[k];
            u64 wA = pack2(w.x, w.x);
            u64 wB = pack2(w.y, w.y);
            ffma2(a01, wA, hv.x);
            ffma2(a23, wA, hv.y);
            ffma2(c01, wB, hv.x);
            ffma2(c23, wB, hv.y);
        }
        float a0, a1, a2, a3, c0, c1, c2, c3;
        unpack2(a0, a1, a01); unpack2(a2, a3, a23);
        unpack2(c0, c1, c01); unpack2(c2, c3, c23);
        size_t base = ((size_t)(t0 + t) * BSZ + b0) * (HSZ / 2) + tid;
        xwo[base]                 = make_float2(a0, c0);
        xwo[base + (HSZ / 2)]     = make_float2(a1, c1);
        xwo[base + 2 * (HSZ / 2)] = make_float2(a2, c2);
        xwo[base + 3 * (HSZ / 2)] = make_float2(a3, c3);
    }
}

// ---------------------------------------------------------------------------
// Kernel 2: clustered persistent recurrence, 512 threads, dual k-groups.
// ---------------------------------------------------------------------------
__global__ __launch_bounds__(NTHR, 1) __cluster_dims__(2, 1, 1)
void rnn_cluster_kernel(const float* __restrict__ Wh,
                        const float* __restrict__ Wd,
                        const float* __restrict__ bd,
                        float* __restrict__ out)
{
    extern __shared__ float smem[];
    float*  whc  = smem;                              // [2][KCG][512]
    float*  hsm  = whc + 2 * KCG * HSZ;               // [KH][KSTRIDE]
    float*  xbf  = hsm + KH * KSTRIDE;                // [2][128][16]
    float4* red  = reinterpret_cast<float4*>(xbf + 2 * 128 * 16);  // [4][256]
    float*  wd_s = reinterpret_cast<float*>(red + 4 * 256);        // [512]

    const int tid = threadIdx.x;
    uint32_t rank;
    asm("mov.u32 %0, %%cluster_ctarank;" : "=r"(rank));
    const uint32_t peer = rank ^ 1u;
    const int b0  = (blockIdx.x >> 1) * CROWS;
    const int wg  = tid >> 8;            // k-group 0/1
    const int lp2 = tid & 255;           // col-pair index (cols 2lp2, 2lp2+1)
    const bool g0  = (wg == 0);
    const bool own = g0 && ((lp2 >> 7) == (int)rank);
    const int  lp  = lp2 & 127;

    // ---- preload cached W_h rows (both groups) and W_d ----
    {
        const float4* s0 = reinterpret_cast<const float4*>(Wh + ((size_t)rank * KH) * HSZ);
        const float4* s1 = reinterpret_cast<const float4*>(Wh + ((size_t)rank * KH + 128) * HSZ);
        float4* d = reinterpret_cast<float4*>(whc);
        #pragma unroll 4
        for (int i = tid; i < KCG * HSZ / 4; i += NTHR) {
            d[i] = s0[i];
            d[i + KCG * HSZ / 4] = s1[i];
        }
        wd_s[tid] = Wd[tid];
    }
    __syncthreads();

    const float2* wc2 = reinterpret_cast<const float2*>(whc + wg * KCG * HSZ) + lp2;
    const float2* wg2 = reinterpret_cast<const float2*>(Wh)
                        + ((size_t)(rank * KH + wg * 128 + KCG)) * (HSZ / 2) + lp2;
    const float*  hgb = hsm + wg * 128 * KSTRIDE;   // this group's h rows
    const float2* xw2 = reinterpret_cast<const float2*>(g_xw);
    const uint32_t xb_base = smem_u32(xbf);

    for (int t = 0; t < TSZ; t++) {
        const int p = t & 1;

        float2 xr[CROWS];
        if (own) {
            #pragma unroll
            for (int r = 0; r < CROWS; r++)
                xr[r] = xw2[((size_t)t * BSZ + b0 + r) * (HSZ / 2) + lp2];
        }

        u64 A01 = 0, A23 = 0, A45 = 0, A67 = 0;
        u64 C01 = 0, C23 = 0, C45 = 0, C67 = 0;

        if (t > 0) {
            // ---- cached rows of this k-group ----
            #pragma unroll 8
            for (int k = 0; k < KCG; k++) {
                float2 w = wc2[k * (HSZ / 2)];
                ulonglong2 hA = *reinterpret_cast<const ulonglong2*>(hgb + k * KSTRIDE);
                ulonglong2 hB = *reinterpret_cast<const ulonglong2*>(hgb + k * KSTRIDE + 4);
                u64 wA = pack2(w.x, w.x), wB = pack2(w.y, w.y);
                ffma2(A01, wA, hA.x); ffma2(A23, wA, hA.y);
                ffma2(A45, wA, hB.x); ffma2(A67, wA, hB.y);
                ffma2(C01, wB, hA.x); ffma2(C23, wB, hA.y);
                ffma2(C45, wB, hB.x); ffma2(C67, wB, hB.y);
            }
            // ---- streamed rows with register prefetch ----
            float2 wreg[UPF];
            #pragma unroll
            for (int u = 0; u < UPF; u++)
                wreg[u] = wg2[u * (HSZ / 2)];

            for (int kb = KCG; kb < 128; kb += UPF) {
                float2 wcur[UPF];
                #pragma unroll
                for (int u = 0; u < UPF; u++) wcur[u] = wreg[u];
                if (kb + UPF < 128) {
                    #pragma unroll
                    for (int u = 0; u < UPF; u++)
                        wreg[u] = wg2[(size_t)(kb - KCG + UPF + u) * (HSZ / 2)];
                }
                #pragma unroll
                for (int u = 0; u < UPF; u++) {
                    int k = kb + u;
                    ulonglong2 hA = *reinterpret_cast<const ulonglong2*>(hgb + k * KSTRIDE);
                    ulonglong2 hB = *reinterpret_cast<const ulonglong2*>(hgb + k * KSTRIDE + 4);
                    u64 wA = pack2(wcur[u].x, wcur[u].x), wB = pack2(wcur[u].y, wcur[u].y);
                    ffma2(A01, wA, hA.x); ffma2(A23, wA, hA.y);
                    ffma2(A45, wA, hB.x); ffma2(A67, wA, hB.y);
                    ffma2(C01, wB, hA.x); ffma2(C23, wB, hA.y);
                    ffma2(C45, wB, hB.x); ffma2(C67, wB, hB.y);
                }
            }
        }

        float a0, a1, a2, a3, a4, a5, a6, a7;
        float c0, c1, c2, c3, c4, c5, c6, c7;
        unpack2(a0, a1, A01); unpack2(a2, a3, A23);
        unpack2(a4, a5, A45); unpack2(a6, a7, A67);
        unpack2(c0, c1, C01); unpack2(c2, c3, C23);
        unpack2(c4, c5, C45); unpack2(c6, c7, C67);

        // ---- wg1 -> wg0 reduction via conflict-free float4 scratch ----
        if (!g0) {
            red[0 * 256 + lp2] = make_float4(a0, a1, a2, a3);
            red[1 * 256 + lp2] = make_float4(a4, a5, a6, a7);
            red[2 * 256 + lp2] = make_float4(c0, c1, c2, c3);
            red[3 * 256 + lp2] = make_float4(c4, c5, c6, c7);
        }
        __syncthreads();   // S1: red visible; also all hsm reads drained

        if (g0) {
            float4 r0 = red[0 * 256 + lp2];
            float4 r1 = red[1 * 256 + lp2];
            float4 r2 = red[2 * 256 + lp2];
            float4 r3 = red[3 * 256 + lp2];
            a0 += r0.x; a1 += r0.y; a2 += r0.z; a3 += r0.w;
            a4 += r1.x; a5 += r1.y; a6 += r1.z; a7 += r1.w;
            c0 += r2.x; c1 += r2.y; c2 += r2.z; c3 += r2.w;
            c4 += r3.x; c5 += r3.y; c6 += r3.z; c7 += r3.w;

            if (!own) {
                float4* dst = reinterpret_cast<float4*>(xbf) + (p * 128 + lp) * 4;
                dst[0] = make_float4(a0, a1, a2, a3);
                dst[1] = make_float4(a4, a5, a6, a7);
                dst[2] = make_float4(c0, c1, c2, c3);
                dst[3] = make_float4(c4, c5, c6, c7);
            }
        }

        CLUSTER_SYNC();   // peer's foreign partials visible

        if (own) {
            uint32_t pa = mapa_peer(xb_base + (uint32_t)(p * 128 + lp) * 64, peer);
            float4 q0 = ld_cluster_f4(pa);
            float4 q1 = ld_cluster_f4(pa + 16);
            float4 q2 = ld_cluster_f4(pa + 32);
            float4 q3 = ld_cluster_f4(pa + 48);

            const int jlA = 2 * lp, jlB = jlA + 1;
            float* hA = hsm + jlA * KSTRIDE;
            float* hB = hsm + jlB * KSTRIDE;
            *reinterpret_cast<float4*>(hA) = make_float4(
                fmaxf(a0 + q0.x + xr[0].x, 0.f), fmaxf(a1 + q0.y + xr[1].x, 0.f),
                fmaxf(a2 + q0.z + xr[2].x, 0.f), fmaxf(a3 + q0.w + xr[3].x, 0.f));
            *reinterpret_cast<float4*>(hA + 4) = make_float4(
                fmaxf(a4 + q1.x + xr[4].x, 0.f), fmaxf(a5 + q1.y + xr[5].x, 0.f),
                fmaxf(a6 + q1.z + xr[6].x, 0.f), fmaxf(a7 + q1.w + xr[7].x, 0.f));
            *reinterpret_cast<float4*>(hB) = make_float4(
                fmaxf(c0 + q2.x + xr[0].y, 0.f), fmaxf(c1 + q2.y + xr[1].y, 0.f),
                fmaxf(c2 + q2.z + xr[2].y, 0.f), fmaxf(c3 + q2.w + xr[3].y, 0.f));
            *reinterpret_cast<float4*>(hB + 4) = make_float4(
                fmaxf(c4 + q3.x + xr[4].y, 0.f), fmaxf(c5 + q3.y + xr[5].y, 0.f),
                fmaxf(c6 + q3.z + xr[6].y, 0.f), fmaxf(c7 + q3.w + xr[7].y, 0.f));
        }
        __syncthreads();   // S2: h_t visible CTA-wide
    }

    // ---- final dense: out[b] = relu(h_T[b,:] @ W_d + b_d) ----
    {
        float s = 0.f;
        if (tid < 256) {
            const int wr = tid >> 5;      // warp 0..7 -> batch row
            const int l  = tid & 31;
            #pragma unroll
            for (int i = 0; i < 8; i++) {
                int jl = l * 8 + i;
                s += hsm[jl * KSTRIDE + wr] * wd_s[rank * KH + jl];
            }
            #pragma unroll
            for (int off = 16; off > 0; off >>= 1)
                s += __shfl_xor_sync(0xffffffffu, s, off);
            if (rank == 1 && l == 0) xbf[wr] = s;
        }
        CLUSTER_SYNC();
        if (rank == 0 && tid < 256 && (tid & 31) == 0) {
            int wr = tid >> 5;
            float sp = ld_cluster_f32(mapa_peer(xb_base + (uint32_t)wr * 4, peer));
            out[b0 + wr] = fmaxf(s + sp + bd[0], 0.f);
        }
        CLUSTER_SYNC();   // keep peer smem alive until reads complete
    }
}

extern "C" void kernel_launch(void* const* d_in, const int* in_sizes, int n_in,
                              void* d_out, int out_size) {
    const float* x    = (const float*)d_in[0];
    const float* Wx   = (const float*)d_in[1];
    const float* Wh   = (const float*)d_in[2];
    const float* brnn = (const float*)d_in[3];
    const float* Wd   = (const float*)d_in[4];
    const float* bd   = (const float*)d_in[5];
    float* out = (float*)d_out;

    cudaFuncSetAttribute(xw_kernel,
                         cudaFuncAttributeMaxDynamicSharedMemorySize, SMEM_XW_BYTES);
    cudaFuncSetAttribute(rnn_cluster_kernel,
                         cudaFuncAttributeMaxDynamicSharedMemorySize, SMEM_MAIN_BYTES);

    dim3 gxw(TSZ / TT, BSZ / 4);
    xw_kernel<<<gxw, NTHRX, SMEM_XW_BYTES>>>(x, Wx, brnn);
    rnn_cluster_kernel<<<NCTA, NTHR, SMEM_MAIN_BYTES>>>(Wh, Wd, bd, out);
}

// round 14
// speedup vs baseline: 1.0014x; 1.0014x over previous
#include <cuda_runtime.h>
#include <cstdint>

// RNN: B=512, T=512, D=64, H=512, O=1
// R8: cluster k-split (2 CTAs) + 4 intra-CTA k-groups x 128 thr (512 thr).
//  Thread tile = 4 cols x 8 rows (16 u64 accs, FFMA2). w loads float4.
//  Groups 1-3 reduce into group 0 via conflict-free float4 scratch.
//  DSMEM exchange of foreign j-half (double-buffered by t parity).

#define BSZ 512
#define TSZ 512
#define DSZ 64
#define HSZ 512
#define KH  256       // k-rows per CTA (cluster half)
#define CROWS 8
#define NTHR 512
#define NCTA 128
#define NG   4        // k-groups per CTA
#define KG   64       // k-rows per group
#define KCG  16       // cached rows per group
#define UPF  4        // prefetch depth; (KG-KCG)%UPF==0
#define KSTRIDE 12    // h smem k-stride (floats); 3 16B-chunks (odd -> conflict-free)

// smem floats: whc 4*16*512=32768 | hsm 256*12=3072 | xbf 2*8*64*4=4096
//              red 3*8*128*4=12288 | wd 512  -> 52736 f = 210944 B
#define SMEM_MAIN_BYTES ((NG*KCG*HSZ + KH*KSTRIDE + 2*8*64*4 + 3*8*128*4 + 512) * 4)

#define TT 16
#define NTHRX 256
#define SMEM_XW_BYTES ((DSZ * HSZ + TT * DSZ * 4) * 4)

__device__ float g_xw[(size_t)TSZ * BSZ * HSZ];   // [T][B][H]

typedef unsigned long long u64;

__device__ __forceinline__ void ffma2(u64& acc, u64 a, u64 b) {
    asm("fma.rn.f32x2 %0, %1, %2, %0;" : "+l"(acc) : "l"(a), "l"(b));
}
__device__ __forceinline__ u64 pack2(float lo, float hi) {
    u64 r; asm("mov.b64 %0, {%1, %2};" : "=l"(r) : "f"(lo), "f"(hi)); return r;
}
__device__ __forceinline__ void unpack2(float& lo, float& hi, u64 v) {
    asm("mov.b64 {%0, %1}, %2;" : "=f"(lo), "=f"(hi) : "l"(v));
}
__device__ __forceinline__ float4 u64pair_f4(u64 a, u64 b) {
    float4 v;
    unpack2(v.x, v.y, a);
    unpack2(v.z, v.w, b);
    return v;
}
__device__ __forceinline__ uint32_t smem_u32(const void* p) {
    uint32_t a;
    asm("{ .reg .u64 t; cvta.to.shared.u64 t, %1; cvt.u32.u64 %0, t; }"
        : "=r"(a) : "l"(p));
    return a;
}
__device__ __forceinline__ uint32_t mapa_peer(uint32_t addr, uint32_t peer) {
    uint32_t r;
    asm("mapa.shared::cluster.u32 %0, %1, %2;" : "=r"(r) : "r"(addr), "r"(peer));
    return r;
}
__device__ __forceinline__ float4 ld_cluster_f4(uint32_t a) {
    float4 v;
    asm volatile("ld.shared::cluster.v4.f32 {%0,%1,%2,%3}, [%4];"
                 : "=f"(v.x), "=f"(v.y), "=f"(v.z), "=f"(v.w) : "r"(a));
    return v;
}
__device__ __forceinline__ float ld_cluster_f32(uint32_t a) {
    float v;
    asm volatile("ld.shared::cluster.f32 %0, [%1];" : "=f"(v) : "r"(a));
    return v;
}
#define CLUSTER_SYNC() do { \
    asm volatile("barrier.cluster.arrive.aligned;" ::: "memory"); \
    asm volatile("barrier.cluster.wait.aligned;"   ::: "memory"); \
} while (0)

// fused quad: acc[0..3] (rows 01,23,45,67 of one col) += {w,w} * h pairs
__device__ __forceinline__ void fq(u64* Ac, float wv, ulonglong2 hA, ulonglong2 hB) {
    u64 wp = pack2(wv, wv);
    ffma2(Ac[0], wp, hA.x);
    ffma2(Ac[1], wp, hA.y);
    ffma2(Ac[2], wp, hB.x);
    ffma2(Ac[3], wp, hB.y);
}

// ---------------------------------------------------------------------------
// Kernel 1: XW = x @ W_x + b_rnn   (unchanged)
// ---------------------------------------------------------------------------
__global__ __launch_bounds__(NTHRX, 1)
void xw_kernel(const float* __restrict__ x,
               const float* __restrict__ Wx,
               const float* __restrict__ brnn)
{
    extern __shared__ float smem[];
    float* wx_s = smem;
    float* xs   = wx_s + DSZ * HSZ;

    const int tid = threadIdx.x;
    const int t0  = blockIdx.x * TT;
    const int b0  = blockIdx.y * 4;

    {
        const float4* g = reinterpret_cast<const float4*>(Wx);
        float4* d = reinterpret_cast<float4*>(wx_s);
        #pragma unroll 8
        for (int i = tid; i < DSZ * HSZ / 4; i += NTHRX) d[i] = g[i];
    }
    #pragma unroll
    for (int i = 0; i < TT * DSZ * 4 / NTHRX; i++) {
        int idx = tid + i * NTHRX;
        int d = idx & 63;
        int t = (idx >> 6) & (TT - 1);
        int r = idx >> 10;
        xs[(t * DSZ + d) * 4 + r] = x[((size_t)(b0 + r) * TSZ + t0 + t) * DSZ + d];
    }
    __syncthreads();

    const float2* wx2 = reinterpret_cast<const float2*>(wx_s) + tid;
    float bA = brnn[2 * tid], bB = brnn[2 * tid + 1];
    u64 bA2 = pack2(bA, bA), bB2 = pack2(bB, bB);

    float2* xwo = reinterpret_cast<float2*>(g_xw);

    for (int t = 0; t < TT; t++) {
        u64 a01 = bA2, a23 = bA2, c01 = bB2, c23 = bB2;
        const ulonglong2* xv = reinterpret_cast<const ulonglong2*>(xs + t * DSZ * 4);
        #pragma unroll 8
        for (int k = 0; k < DSZ; k++) {
            float2 w = wx2[k * (HSZ / 2)];
            ulonglong2 hv = xv[k];
            u64 wA = pack2(w.x, w.x);
            u64 wB = pack2(w.y, w.y);
            ffma2(a01, wA, hv.x);
            ffma2(a23, wA, hv.y);
            ffma2(c01, wB, hv.x);
            ffma2(c23, wB, hv.y);
        }
        float a0, a1, a2, a3, c0, c1, c2, c3;
        unpack2(a0, a1, a01); unpack2(a2, a3, a23);
        unpack2(c0, c1, c01); unpack2(c2, c3, c23);
        size_t base = ((size_t)(t0 + t) * BSZ + b0) * (HSZ / 2) + tid;
        xwo[base]                 = make_float2(a0, c0);
        xwo[base + (HSZ / 2)]     = make_float2(a1, c1);
        xwo[base + 2 * (HSZ / 2)] = make_float2(a2, c2);
        xwo[base + 3 * (HSZ / 2)] = make_float2(a3, c3);
    }
}

// ---------------------------------------------------------------------------
// Kernel 2: clustered persistent recurrence, 512 thr, 4 k-groups, 4-col tile.
// ---------------------------------------------------------------------------
__global__ __launch_bounds__(NTHR, 1) __cluster_dims__(2, 1, 1)
void rnn_cluster_kernel(const float* __restrict__ Wh,
                        const float* __restrict__ Wd,
                        const float* __restrict__ bd,
                        float* __restrict__ out)
{
    extern __shared__ float smem[];
    float*  whc  = smem;                               // [NG][KCG][512]
    float*  hsm  = whc + NG * KCG * HSZ;               // [KH][KSTRIDE]
    float4* xbf4 = reinterpret_cast<float4*>(hsm + KH * KSTRIDE);  // [2][8][64]
    float4* red4 = xbf4 + 2 * 8 * 64;                  // [24][128]
    float*  wd_s = reinterpret_cast<float*>(red4 + 24 * 128);      // [512]

    const int tid = threadIdx.x;
    uint32_t rank;
    asm("mov.u32 %0, %%cluster_ctarank;" : "=r"(rank));
    const uint32_t peer = rank ^ 1u;
    const int b0 = (blockIdx.x >> 1) * CROWS;
    const int g  = tid >> 7;            // k-group 0..3
    const int lq = tid & 127;           // col-quad: cols 4lq..4lq+3
    const bool g0  = (g == 0);
    const bool own = g0 && ((lq >> 6) == (int)rank);
    const int  s6  = lq & 63;

    // ---- preload cached W_h rows (per group) and W_d ----
    {
        #pragma unroll
        for (int gg = 0; gg < NG; gg++) {
            const float4* src = reinterpret_cast<const float4*>(
                Wh + ((size_t)rank * KH + gg * KG) * HSZ);
            float4* dst = reinterpret_cast<float4*>(whc + gg * KCG * HSZ);
            #pragma unroll 2
            for (int i = tid; i < KCG * HSZ / 4; i += NTHR) dst[i] = src[i];
        }
        wd_s[tid & 511] = Wd[tid & 511];
    }
    __syncthreads();

    const float4* wc4 = reinterpret_cast<const float4*>(whc + g * KCG * HSZ) + lq;
    const float4* wg4 = reinterpret_cast<const float4*>(Wh)
                        + ((size_t)(rank * KH + g * KG + KCG)) * (HSZ / 4) + lq;
    const float*  hgb = hsm + g * KG * KSTRIDE;
    const float4* xw4 = reinterpret_cast<const float4*>(g_xw);
    const uint32_t xb_base = smem_u32(xbf4);

    for (int t = 0; t < TSZ; t++) {
        const int p = t & 1;

        u64 A[4][4];
        #pragma unroll
        for (int c = 0; c < 4; c++)
            #pragma unroll
            for (int j = 0; j < 4; j++) A[c][j] = 0ull;

        if (t > 0) {
            // ---- cached rows of this k-group ----
            #pragma unroll 4
            for (int k = 0; k < KCG; k++) {
                float4 w = wc4[k * (HSZ / 4)];
                ulonglong2 hA = *reinterpret_cast<const ulonglong2*>(hgb + k * KSTRIDE);
                ulonglong2 hB = *reinterpret_cast<const ulonglong2*>(hgb + k * KSTRIDE + 4);
                fq(A[0], w.x, hA, hB);
                fq(A[1], w.y, hA, hB);
                fq(A[2], w.z, hA, hB);
                fq(A[3], w.w, hA, hB);
            }
            // ---- streamed rows with register prefetch ----
            float4 wreg[UPF];
            #pragma unroll
            for (int u = 0; u < UPF; u++)
                wreg[u] = wg4[u * (HSZ / 4)];

            for (int kb = KCG; kb < KG; kb += UPF) {
                float4 wcur[UPF];
                #pragma unroll
                for (int u = 0; u < UPF; u++) wcur[u] = wreg[u];
                if (kb + UPF < KG) {
                    #pragma unroll
                    for (int u = 0; u < UPF; u++)
                        wreg[u] = wg4[(size_t)(kb - KCG + UPF + u) * (HSZ / 4)];
                }
                #pragma unroll
                for (int u = 0; u < UPF; u++) {
                    int k = kb + u;
                    ulonglong2 hA = *reinterpret_cast<const ulonglong2*>(hgb + k * KSTRIDE);
                    ulonglong2 hB = *reinterpret_cast<const ulonglong2*>(hgb + k * KSTRIDE + 4);
                    fq(A[0], wcur[u].x, hA, hB);
                    fq(A[1], wcur[u].y, hA, hB);
                    fq(A[2], wcur[u].z, hA, hB);
                    fq(A[3], wcur[u].w, hA, hB);
                }
            }
        }

        // issue xw loads now; consumed after cluster sync (latency overlapped)
        float4 xr[CROWS];
        if (own) {
            #pragma unroll
            for (int r = 0; r < CROWS; r++)
                xr[r] = xw4[((size_t)t * BSZ + b0 + r) * (HSZ / 4) + lq];
        }

        // ---- groups 1-3 -> scratch ----
        if (!g0) {
            #pragma unroll
            for (int c = 0; c < 4; c++)
                #pragma unroll
                for (int h2 = 0; h2 < 2; h2++)
                    red4[((g - 1) * 8 + c * 2 + h2) * 128 + lq] =
                        u64pair_f4(A[c][2 * h2], A[c][2 * h2 + 1]);
        }
        __syncthreads();   // S1: red visible; all hsm reads drained

        float4 F[4][2];
        if (g0) {
            #pragma unroll
            for (int c = 0; c < 4; c++)
                #pragma unroll
                for (int h2 = 0; h2 < 2; h2++) {
                    float4 f = u64pair_f4(A[c][2 * h2], A[c][2 * h2 + 1]);
                    #pragma unroll
                    for (int gg = 0; gg < 3; gg++) {
                        float4 r = red4[(gg * 8 + c * 2 + h2) * 128 + lq];
                        f.x += r.x; f.y += r.y; f.z += r.z; f.w += r.w;
                    }
                    F[c][h2] = f;
                    if (!own)
                        xbf4[(p * 8 + c * 2 + h2) * 64 + s6] = f;
                }
        }

        CLUSTER_SYNC();   // peer's foreign partials visible

        if (own) {
            #pragma unroll
            for (int c = 0; c < 4; c++) {
                const int jl = 4 * s6 + c;
                #pragma unroll
                for (int h2 = 0; h2 < 2; h2++) {
                    uint32_t pa = mapa_peer(
                        xb_base + (uint32_t)((p * 8 + c * 2 + h2) * 64 + s6) * 16, peer);
                    float4 q = ld_cluster_f4(pa);
                    float4 f = F[c][h2];
                    const int r0 = 4 * h2;
                    f.x = fmaxf(f.x + q.x + reinterpret_cast<const float*>(&xr[r0 + 0])[c], 0.f);
                    f.y = fmaxf(f.y + q.y + reinterpret_cast<const float*>(&xr[r0 + 1])[c], 0.f);
                    f.z = fmaxf(f.z + q.z + reinterpret_cast<const float*>(&xr[r0 + 2])[c], 0.f);
                    f.w = fmaxf(f.w + q.w + reinterpret_cast<const float*>(&xr[r0 + 3])[c], 0.f);
                    *reinterpret_cast<float4*>(hsm + jl * KSTRIDE + 4 * h2) = f;
                }
            }
        }
        __syncthreads();   // S2: h_t visible CTA-wide
    }

    // ---- final dense: out[b] = relu(h_T[b,:] @ W_d + b_d) ----
    {
        float s = 0.f;
        if (tid < 256) {
            const int wr = tid >> 5;      // warp 0..7 -> batch row
            const int l  = tid & 31;
            #pragma unroll
            for (int i = 0; i < 8; i++) {
                int jl = l * 8 + i;
                s += hsm[jl * KSTRIDE + wr] * wd_s[rank * KH + jl];
            }
            #pragma unroll
            for (int off = 16; off > 0; off >>= 1)
                s += __shfl_xor_sync(0xffffffffu, s, off);
            if (rank == 1 && l == 0)
                reinterpret_cast<float*>(xbf4)[wr] = s;
        }
        CLUSTER_SYNC();
        if (rank == 0 && tid < 256 && (tid & 31) == 0) {
            int wr = tid >> 5;
            float sp = ld_cluster_f32(mapa_peer(xb_base + (uint32_t)wr * 4, peer));
            out[b0 + wr] = fmaxf(s + sp + bd[0], 0.f);
        }
        CLUSTER_SYNC();   // keep peer smem alive until reads complete
    }
}

extern "C" void kernel_launch(void* const* d_in, const int* in_sizes, int n_in,
                              void* d_out, int out_size) {
    const float* x    = (const float*)d_in[0];
    const float* Wx   = (const float*)d_in[1];
    const float* Wh   = (const float*)d_in[2];
    const float* brnn = (const float*)d_in[3];
    const float* Wd   = (const float*)d_in[4];
    const float* bd   = (const float*)d_in[5];
    float* out = (float*)d_out;

    cudaFuncSetAttribute(xw_kernel,
                         cudaFuncAttributeMaxDynamicSharedMemorySize, SMEM_XW_BYTES);
    cudaFuncSetAttribute(rnn_cluster_kernel,
                         cudaFuncAttributeMaxDynamicSharedMemorySize, SMEM_MAIN_BYTES);

    dim3 gxw(TSZ / TT, BSZ / 4);
    xw_kernel<<<gxw, NTHRX, SMEM_XW_BYTES>>>(x, Wx, brnn);
    rnn_cluster_kernel<<<NCTA, NTHR, SMEM_MAIN_BYTES>>>(Wh, Wd, bd, out);
}